// round 8
// baseline (speedup 1.0000x reference)
#include <cuda_runtime.h>

// ---------------- problem constants ----------------
#define T_STEPS   1024
#define H_DIM     1024
#define B_SZ      16
#define CH_SZ     4
#define R_ROWS    64            // B*CH rows of the state matrix
#define K_IN      256           // CH * D

// ---------------- recurrence kernel config ----------------
#define NCTA      128
#define NC        8             // H_DIM / NCTA columns owned per CTA
#define NTHREADS  128
#define CHUNK     64            // h-chunk staged in SMEM
#define NCHUNKS   (H_DIM / CHUNK)
#define SPITCH    68            // padded row pitch (floats), 16B-aligned rows

// SMEM: Wsm2 (H*NC float2 = 64KB) + double-buffered state chunk (2*CHUNK*SPITCH floats)
#define SMEM_FLOATS (2 * H_DIM * NC + 2 * CHUNK * SPITCH)
#define SMEM_BYTES  (SMEM_FLOATS * 4)

// ---------------- device scratch (static: no allocations allowed) ----------------
__device__ __align__(16) float g_inp[T_STEPS * B_SZ * H_DIM];   // [T][B][H] 64MB
__device__ __align__(16) float g_S[2][H_DIM][R_ROWS];           // h-major state, double buffered
__device__ unsigned int g_bar_count;

// ---------------- packed fp32x2 FMA (FFMA2) ----------------
__device__ __forceinline__ float2 ffma2(float2 a, float2 b, float2 c) {
    unsigned long long au = *reinterpret_cast<unsigned long long*>(&a);
    unsigned long long bu = *reinterpret_cast<unsigned long long*>(&b);
    unsigned long long cu = *reinterpret_cast<unsigned long long*>(&c);
    asm("fma.rn.f32x2 %0, %1, %2, %0;" : "+l"(cu) : "l"(au), "l"(bu));
    return *reinterpret_cast<float2*>(&cu);
}

// ---------------- grid barrier (monotonic count, reset via memset each launch) ----
__device__ __forceinline__ void grid_barrier(unsigned int* phase) {
    __syncthreads();
    __threadfence();
    if (threadIdx.x == 0) {
        *phase += 1;
        unsigned int target = *phase * NCTA;
        atomicAdd(&g_bar_count, 1u);
        while (*((volatile unsigned int*)&g_bar_count) < target) { }
    }
    __syncthreads();
    __threadfence();
}

// =====================================================================
// Kernel A: inp[t][b][h] = sum_f u[t][b][f] * W_in[h][f]
//   u[t][b][f] = x[b][f/64][t][f%64]
//   M = T*B = 16384 (row m = t*16 + b), N = H = 1024, K = 256
// =====================================================================
__global__ void __launch_bounds__(256) inp_gemm_kernel(const float* __restrict__ x,
                                                       const float* __restrict__ Win) {
    __shared__ float Asm[64][SPITCH];
    __shared__ float Bsm[64][SPITCH];

    const int tid = threadIdx.x;
    const int m0 = blockIdx.x * 64;
    const int n0 = blockIdx.y * 64;

    const int rl = tid >> 2;      // 0..63  (row within tile for loading)
    const int kq = tid & 3;       // 16-wide k band

    const int txx = tid & 15;     // 0..15 -> 4 output cols
    const int tyy = tid >> 4;     // 0..15 -> 4 output rows

    float acc[4][4];
#pragma unroll
    for (int i = 0; i < 4; ++i)
#pragma unroll
        for (int p = 0; p < 4; ++p) acc[i][p] = 0.0f;

    const int m = m0 + rl;
    const int tt = m >> 4;        // time index
    const int bb = m & 15;        // batch index

    for (int kc = 0; kc < 4; ++kc) {          // K chunks of 64 (== one channel block)
        __syncthreads();
        // A tile: rows of u, chunk kc maps exactly to channel kc, d = kk
        const float* xrow = x + ((size_t)(bb * CH_SZ + kc) * T_STEPS + tt) * 64;
        const float* wrow = Win + (size_t)(n0 + rl) * K_IN + kc * 64;
#pragma unroll
        for (int q = 0; q < 4; ++q) {
            int kk = kq * 16 + q * 4;
            *reinterpret_cast<float4*>(&Asm[rl][kk]) =
                *reinterpret_cast<const float4*>(&xrow[kk]);
            *reinterpret_cast<float4*>(&Bsm[rl][kk]) =
                *reinterpret_cast<const float4*>(&wrow[kk]);
        }
        __syncthreads();

#pragma unroll 8
        for (int kk = 0; kk < 64; ++kk) {
            float a0 = Asm[4 * tyy + 0][kk];
            float a1 = Asm[4 * tyy + 1][kk];
            float a2 = Asm[4 * tyy + 2][kk];
            float a3 = Asm[4 * tyy + 3][kk];
            float b0 = Bsm[4 * txx + 0][kk];
            float b1 = Bsm[4 * txx + 1][kk];
            float b2 = Bsm[4 * txx + 2][kk];
            float b3 = Bsm[4 * txx + 3][kk];
            acc[0][0] = fmaf(a0, b0, acc[0][0]); acc[0][1] = fmaf(a0, b1, acc[0][1]);
            acc[0][2] = fmaf(a0, b2, acc[0][2]); acc[0][3] = fmaf(a0, b3, acc[0][3]);
            acc[1][0] = fmaf(a1, b0, acc[1][0]); acc[1][1] = fmaf(a1, b1, acc[1][1]);
            acc[1][2] = fmaf(a1, b2, acc[1][2]); acc[1][3] = fmaf(a1, b3, acc[1][3]);
            acc[2][0] = fmaf(a2, b0, acc[2][0]); acc[2][1] = fmaf(a2, b1, acc[2][1]);
            acc[2][2] = fmaf(a2, b2, acc[2][2]); acc[2][3] = fmaf(a2, b3, acc[2][3]);
            acc[3][0] = fmaf(a3, b0, acc[3][0]); acc[3][1] = fmaf(a3, b1, acc[3][1]);
            acc[3][2] = fmaf(a3, b2, acc[3][2]); acc[3][3] = fmaf(a3, b3, acc[3][3]);
        }
    }

#pragma unroll
    for (int i = 0; i < 4; ++i) {
        float4 v = make_float4(acc[i][0], acc[i][1], acc[i][2], acc[i][3]);
        *reinterpret_cast<float4*>(
            &g_inp[(size_t)(m0 + 4 * tyy + i) * H_DIM + n0 + 4 * txx]) = v;
    }
}

// =====================================================================
// Kernel B: persistent recurrence over T steps.
//   Each CTA owns output columns [n0, n0+8). State stored h-major in g_S.
// =====================================================================
__device__ __forceinline__ void load_chunk(const float* __restrict__ Sprev, int c,
                                           float* __restrict__ dst) {
    const int tid = threadIdx.x;
    const float4* src = reinterpret_cast<const float4*>(Sprev + c * CHUNK * R_ROWS);
    float4 v[8];
#pragma unroll
    for (int i = 0; i < 8; ++i) v[i] = __ldcg(src + tid + i * NTHREADS);
#pragma unroll
    for (int i = 0; i < 8; ++i) {
        int f = tid + i * NTHREADS;       // float4 index within chunk
        int hl = f >> 4;                  // 16 float4 per h-row (64 floats)
        int r4 = f & 15;
        *reinterpret_cast<float4*>(dst + hl * SPITCH + r4 * 4) = v[i];
    }
}

extern __shared__ float sm_b[];

__global__ void __launch_bounds__(NTHREADS, 1) esn_recur_kernel(
        const float* __restrict__ W_res, float* __restrict__ out) {
    float2* Wsm2 = reinterpret_cast<float2*>(sm_b);          // [h*NC + j] duplicated weights
    float*  Ssm  = sm_b + 2 * H_DIM * NC;                    // [2][CHUNK][SPITCH]

    const int tid = threadIdx.x;
    const int n0  = blockIdx.x * NC;
    const int j   = tid & (NC - 1);        // owned column within slice
    const int rg  = tid >> 3;              // 0..15 -> rows 4rg..4rg+3

    // Preload W_res column slice, duplicated into both f32x2 lanes.
    for (int h = rg; h < H_DIM; h += 16) {
        float w = W_res[(size_t)h * H_DIM + n0 + j];
        Wsm2[h * NC + j] = make_float2(w, w);
    }
    // Zero own slice of state buffer 0.
    for (int i = tid; i < NC * R_ROWS; i += NTHREADS) {
        g_S[0][n0 + (i >> 6)][i & 63] = 0.0f;
    }
    __syncthreads();

    unsigned int phase = 0;
    grid_barrier(&phase);                   // all state zeroed + visible

    for (int t = 0; t < T_STEPS; ++t) {
        const float* Sprev = &g_S[t & 1][0][0];
        float*       Snext = &g_S[(t + 1) & 1][0][0];

        float2 acc01 = make_float2(0.0f, 0.0f);
        float2 acc23 = make_float2(0.0f, 0.0f);

        load_chunk(Sprev, 0, Ssm);          // chunk 0 into buffer 0
        __syncthreads();

#pragma unroll 1
        for (int c = 0; c < NCHUNKS; ++c) {
            if (c + 1 < NCHUNKS)
                load_chunk(Sprev, c + 1, Ssm + ((c + 1) & 1) * (CHUNK * SPITCH));

            const float*  Sp = Ssm + (c & 1) * (CHUNK * SPITCH) + 4 * rg;
            const float2* Wp = Wsm2 + c * CHUNK * NC + j;
#pragma unroll 8
            for (int hl = 0; hl < CHUNK; ++hl) {
                float4 s  = *reinterpret_cast<const float4*>(Sp + hl * SPITCH);
                float2 w2 = Wp[hl * NC];
                acc01 = ffma2(make_float2(s.x, s.y), w2, acc01);
                acc23 = ffma2(make_float2(s.z, s.w), w2, acc23);
            }
            __syncthreads();
        }

        // ---- epilogue: leaky tanh update for 4 owned rows x 1 owned column ----
        float inp_v = g_inp[(size_t)(t * B_SZ + rg) * H_DIM + n0 + j];  // b == rg
        float4 sp = __ldcg(reinterpret_cast<const float4*>(
                        Sprev + (n0 + j) * R_ROWS + 4 * rg));
        float4 o;
        o.x = 0.9f * tanhf(inp_v + acc01.x) + 0.1f * sp.x;
        o.y = 0.9f * tanhf(inp_v + acc01.y) + 0.1f * sp.y;
        o.z = 0.9f * tanhf(inp_v + acc23.x) + 0.1f * sp.z;
        o.w = 0.9f * tanhf(inp_v + acc23.y) + 0.1f * sp.w;

        *reinterpret_cast<float4*>(Snext + (n0 + j) * R_ROWS + 4 * rg) = o;

        // out[b][c][t][h] with row r = 4*rg + i: stride T*H between rows
        size_t ob = ((size_t)(4 * rg) * T_STEPS + t) * H_DIM + n0 + j;
        const size_t RS = (size_t)T_STEPS * H_DIM;
        out[ob]          = o.x;
        out[ob + RS]     = o.y;
        out[ob + 2 * RS] = o.z;
        out[ob + 3 * RS] = o.w;

        grid_barrier(&phase);
    }
}

// =====================================================================
// launch
// =====================================================================
extern "C" void kernel_launch(void* const* d_in, const int* in_sizes, int n_in,
                              void* d_out, int out_size) {
    const float* x    = (const float*)d_in[0];   // [16,4,1024,64]
    const float* Win  = (const float*)d_in[1];   // [1024,256]
    const float* Wres = (const float*)d_in[2];   // [1024,1024]
    float* out = (float*)d_out;                  // [16,4,1024,1024]

    cudaFuncSetAttribute(esn_recur_kernel,
                         cudaFuncAttributeMaxDynamicSharedMemorySize, SMEM_BYTES);

    // input projection (off critical path)
    inp_gemm_kernel<<<dim3(256, 16), 256>>>(x, Win);

    // reset grid barrier counter (captured as a memset node)
    void* bp = nullptr;
    cudaGetSymbolAddress(&bp, g_bar_count);
    cudaMemsetAsync(bp, 0, sizeof(unsigned int));

    // persistent recurrence
    esn_recur_kernel<<<NCTA, NTHREADS, SMEM_BYTES>>>(Wres, out);
}

// round 9
// speedup vs baseline: 1.1587x; 1.1587x over previous
#include <cuda_runtime.h>

// ---------------- problem constants ----------------
#define T_STEPS   1024
#define H_DIM     1024
#define B_SZ      16
#define CH_SZ     4
#define R_ROWS    64            // B*CH rows of the state matrix
#define K_IN      256           // CH * D

// ---------------- recurrence kernel config ----------------
#define NCTA      128
#define NC        8             // H_DIM / NCTA columns owned per CTA
#define NTHREADS  512           // 16 warps: 4 h-split groups of 128 threads
#define NSPLIT    4
#define CHUNK     128           // h-chunk staged in SMEM
#define NCHUNKS   (H_DIM / CHUNK)       // 8
#define HSUB      (CHUNK / NSPLIT)      // 32 h per thread per chunk
#define SPITCH    68            // padded row pitch (floats), 16B-aligned rows

#define W_FLOATS     (2 * H_DIM * NC)        // duplicated weights: 16384 floats (64KB)
#define STAGE_FLOATS (2 * CHUNK * SPITCH)    // double-buffered chunk: 17408 floats
#define PART_FLOATS  (4 * NSPLIT * 128)      // transposed partial sums: 2048 floats
#define SMEM_FLOATS  (W_FLOATS + STAGE_FLOATS + PART_FLOATS)
#define SMEM_BYTES   (SMEM_FLOATS * 4)       // 143360 B

// ---------------- device scratch (static: no allocations allowed) ----------------
__device__ __align__(16) float g_inp[T_STEPS * B_SZ * H_DIM];   // [T][B][H]
__device__ __align__(16) float g_S[2][H_DIM][R_ROWS];           // h-major state, double buffered
__device__ unsigned int g_bar_count;

// ---------------- packed fp32x2 FMA (FFMA2) ----------------
__device__ __forceinline__ float2 ffma2(float2 a, float2 b, float2 c) {
    unsigned long long au = *reinterpret_cast<unsigned long long*>(&a);
    unsigned long long bu = *reinterpret_cast<unsigned long long*>(&b);
    unsigned long long cu = *reinterpret_cast<unsigned long long*>(&c);
    asm("fma.rn.f32x2 %0, %1, %2, %0;" : "+l"(cu) : "l"(au), "l"(bu));
    return *reinterpret_cast<float2*>(&cu);
}

// =====================================================================
// Kernel A: inp[t][b][h] = sum_f u[t][b][f] * W_in[h][f]
// =====================================================================
__global__ void __launch_bounds__(256) inp_gemm_kernel(const float* __restrict__ x,
                                                       const float* __restrict__ Win) {
    __shared__ float Asm[64][SPITCH];
    __shared__ float Bsm[64][SPITCH];

    const int tid = threadIdx.x;
    const int m0 = blockIdx.x * 64;
    const int n0 = blockIdx.y * 64;

    const int rl = tid >> 2;
    const int kq = tid & 3;

    const int txx = tid & 15;
    const int tyy = tid >> 4;

    float acc[4][4];
#pragma unroll
    for (int i = 0; i < 4; ++i)
#pragma unroll
        for (int p = 0; p < 4; ++p) acc[i][p] = 0.0f;

    const int m = m0 + rl;
    const int tt = m >> 4;
    const int bb = m & 15;

    for (int kc = 0; kc < 4; ++kc) {
        __syncthreads();
        const float* xrow = x + ((size_t)(bb * CH_SZ + kc) * T_STEPS + tt) * 64;
        const float* wrow = Win + (size_t)(n0 + rl) * K_IN + kc * 64;
#pragma unroll
        for (int q = 0; q < 4; ++q) {
            int kk = kq * 16 + q * 4;
            *reinterpret_cast<float4*>(&Asm[rl][kk]) =
                *reinterpret_cast<const float4*>(&xrow[kk]);
            *reinterpret_cast<float4*>(&Bsm[rl][kk]) =
                *reinterpret_cast<const float4*>(&wrow[kk]);
        }
        __syncthreads();

#pragma unroll 8
        for (int kk = 0; kk < 64; ++kk) {
            float a0 = Asm[4 * tyy + 0][kk];
            float a1 = Asm[4 * tyy + 1][kk];
            float a2 = Asm[4 * tyy + 2][kk];
            float a3 = Asm[4 * tyy + 3][kk];
            float b0 = Bsm[4 * txx + 0][kk];
            float b1 = Bsm[4 * txx + 1][kk];
            float b2 = Bsm[4 * txx + 2][kk];
            float b3 = Bsm[4 * txx + 3][kk];
            acc[0][0] = fmaf(a0, b0, acc[0][0]); acc[0][1] = fmaf(a0, b1, acc[0][1]);
            acc[0][2] = fmaf(a0, b2, acc[0][2]); acc[0][3] = fmaf(a0, b3, acc[0][3]);
            acc[1][0] = fmaf(a1, b0, acc[1][0]); acc[1][1] = fmaf(a1, b1, acc[1][1]);
            acc[1][2] = fmaf(a1, b2, acc[1][2]); acc[1][3] = fmaf(a1, b3, acc[1][3]);
            acc[2][0] = fmaf(a2, b0, acc[2][0]); acc[2][1] = fmaf(a2, b1, acc[2][1]);
            acc[2][2] = fmaf(a2, b2, acc[2][2]); acc[2][3] = fmaf(a2, b3, acc[2][3]);
            acc[3][0] = fmaf(a3, b0, acc[3][0]); acc[3][1] = fmaf(a3, b1, acc[3][1]);
            acc[3][2] = fmaf(a3, b2, acc[3][2]); acc[3][3] = fmaf(a3, b3, acc[3][3]);
        }
    }

#pragma unroll
    for (int i = 0; i < 4; ++i) {
        float4 v = make_float4(acc[i][0], acc[i][1], acc[i][2], acc[i][3]);
        *reinterpret_cast<float4*>(
            &g_inp[(size_t)(m0 + 4 * tyy + i) * H_DIM + n0 + 4 * txx]) = v;
    }
}

// =====================================================================
// Kernel B: persistent recurrence, 512 threads (4-way h-split per CTA).
// =====================================================================
__device__ __forceinline__ void load_chunk(const float* __restrict__ Sprev, int c,
                                           float* __restrict__ dst) {
    const int tid = threadIdx.x;
    const float4* src = reinterpret_cast<const float4*>(Sprev + c * CHUNK * R_ROWS);
    float4 v[4];
#pragma unroll
    for (int i = 0; i < 4; ++i) v[i] = __ldcg(src + tid + i * NTHREADS);
#pragma unroll
    for (int i = 0; i < 4; ++i) {
        int f = tid + i * NTHREADS;       // float4 index within chunk
        int hl = f >> 4;                  // 16 float4 per h-row (64 floats)
        int r4 = f & 15;
        *reinterpret_cast<float4*>(dst + hl * SPITCH + r4 * 4) = v[i];
    }
}

extern __shared__ float sm_b[];

__global__ void __launch_bounds__(NTHREADS, 1) esn_recur_kernel(
        const float* __restrict__ W_res, float* __restrict__ out) {
    float2* Wsm2 = reinterpret_cast<float2*>(sm_b);          // [h*NC + j] duplicated
    float*  Ssm  = sm_b + W_FLOATS;                          // [2][CHUNK][SPITCH]
    float*  Part = sm_b + W_FLOATS + STAGE_FLOATS;           // [4 comp][4 s][128]

    const int tid = threadIdx.x;
    const int n0  = blockIdx.x * NC;
    const int j   = tid & (NC - 1);        // owned column within slice
    const int rg  = (tid >> 3) & 15;       // row group: rows 4rg..4rg+3
    const int s   = tid >> 7;              // h-split group 0..3
    const int idx128 = tid & 127;          // (rg, j) identity

    // Preload W_res column slice, duplicated into both f32x2 lanes.
    for (int idx = tid; idx < H_DIM * NC; idx += NTHREADS) {
        int h = idx >> 3, jj = idx & 7;
        float w = W_res[(size_t)h * H_DIM + n0 + jj];
        Wsm2[idx] = make_float2(w, w);
    }
    // Zero own slice of state buffer 0.
    for (int i = tid; i < NC * R_ROWS; i += NTHREADS) {
        g_S[0][n0 + (i >> 6)][i & 63] = 0.0f;
    }
    __syncthreads();

    unsigned int phase = 0;
    // initial grid barrier: state zeroed + visible
    __threadfence();
    __syncthreads();
    if (tid == 0) {
        phase = 1;
        atomicAdd(&g_bar_count, 1u);
        while (*((volatile unsigned int*)&g_bar_count) < phase * NCTA) { }
    }
    __syncthreads();
    __threadfence();

    const size_t RS = (size_t)T_STEPS * H_DIM;

    for (int t = 0; t < T_STEPS; ++t) {
        const float* Sprev = &g_S[t & 1][0][0];
        float*       Snext = &g_S[(t + 1) & 1][0][0];

        float2 acc01 = make_float2(0.0f, 0.0f);
        float2 acc23 = make_float2(0.0f, 0.0f);

        load_chunk(Sprev, 0, Ssm);
        __syncthreads();

#pragma unroll 1
        for (int c = 0; c < NCHUNKS; ++c) {
            if (c + 1 < NCHUNKS)
                load_chunk(Sprev, c + 1, Ssm + ((c + 1) & 1) * (CHUNK * SPITCH));

            const float*  Sp = Ssm + (c & 1) * (CHUNK * SPITCH)
                                   + (s * HSUB) * SPITCH + 4 * rg;
            const float2* Wp = Wsm2 + (c * CHUNK + s * HSUB) * NC + j;
#pragma unroll 8
            for (int hl = 0; hl < HSUB; ++hl) {
                float4 sv = *reinterpret_cast<const float4*>(Sp + hl * SPITCH);
                float2 w2 = Wp[hl * NC];
                acc01 = ffma2(make_float2(sv.x, sv.y), w2, acc01);
                acc23 = ffma2(make_float2(sv.z, sv.w), w2, acc23);
            }
            __syncthreads();
        }

        // ---- transposed partial exchange: comp i, group s, (rg,j) ----
        Part[0 * (NSPLIT * 128) + s * 128 + idx128] = acc01.x;
        Part[1 * (NSPLIT * 128) + s * 128 + idx128] = acc01.y;
        Part[2 * (NSPLIT * 128) + s * 128 + idx128] = acc23.x;
        Part[3 * (NSPLIT * 128) + s * 128 + idx128] = acc23.y;
        __syncthreads();

        // each thread owns component i == s (row r = 4*rg + s), sums 4 h-groups
        const float* Pc = Part + s * (NSPLIT * 128) + idx128;
        float sum = Pc[0] + Pc[128] + Pc[256] + Pc[384];

        const int r = 4 * rg + s;
        float inp_v = g_inp[(size_t)(t * B_SZ + rg) * H_DIM + n0 + j];  // b == rg
        float sp = __ldcg(Sprev + (size_t)(n0 + j) * R_ROWS + r);
        float val = 0.9f * tanhf(inp_v + sum) + 0.1f * sp;

        Snext[(size_t)(n0 + j) * R_ROWS + r] = val;

        // ---- barrier arrive (state visible), overlap out store with wait ----
        __threadfence();
        __syncthreads();
        if (tid == 0) {
            phase += 1;
            atomicAdd(&g_bar_count, 1u);
        }

        // out[b][c][t][h], row r maps to (b=r>>2, c=r&3): offset r*T*H
        out[(size_t)r * RS + (size_t)t * H_DIM + n0 + j] = val;

        if (tid == 0) {
            unsigned int target = phase * NCTA;
            while (*((volatile unsigned int*)&g_bar_count) < target) { }
        }
        __syncthreads();
        __threadfence();
    }
}

// =====================================================================
// launch
// =====================================================================
extern "C" void kernel_launch(void* const* d_in, const int* in_sizes, int n_in,
                              void* d_out, int out_size) {
    const float* x    = (const float*)d_in[0];   // [16,4,1024,64]
    const float* Win  = (const float*)d_in[1];   // [1024,256]
    const float* Wres = (const float*)d_in[2];   // [1024,1024]
    float* out = (float*)d_out;                  // [16,4,1024,1024]

    cudaFuncSetAttribute(esn_recur_kernel,
                         cudaFuncAttributeMaxDynamicSharedMemorySize, SMEM_BYTES);

    // input projection (off critical path)
    inp_gemm_kernel<<<dim3(256, 16), 256>>>(x, Win);

    // reset grid barrier counter (captured as a memset node)
    void* bp = nullptr;
    cudaGetSymbolAddress(&bp, g_bar_count);
    cudaMemsetAsync(bp, 0, sizeof(unsigned int));

    // persistent recurrence
    esn_recur_kernel<<<NCTA, NTHREADS, SMEM_BYTES>>>(Wres, out);
}

// round 10
// speedup vs baseline: 1.7302x; 1.4932x over previous
#include <cuda_runtime.h>

// ---------------- problem constants ----------------
#define T_STEPS   1024
#define H_DIM     1024
#define B_SZ      16
#define CH_SZ     4
#define R_ROWS    64            // B*CH rows of the state matrix
#define K_IN      256           // CH * D

// ---------------- recurrence kernel config ----------------
#define NCTA      128
#define NC        8             // H_DIM / NCTA columns owned per CTA
#define NTHREADS  512           // 16 warps
#define NW        16
#define CHUNK     128           // h-chunk staged in SMEM
#define NCHUNKS   (H_DIM / CHUNK)       // 8
#define KPW       (CHUNK / NW)          // 8 k-iters per warp per chunk

// SMEM floats: duplicated weights [1024][8]float2 = 16384
//              state double buffer 2*128*64        = 16384
//              partials 16 warps * 512             = 8192
#define W_FLOATS     (H_DIM * NC * 2)
#define STAGE_FLOATS (2 * CHUNK * R_ROWS)
#define PART_FLOATS  (NW * R_ROWS * NC)
#define SMEM_FLOATS  (W_FLOATS + STAGE_FLOATS + PART_FLOATS)
#define SMEM_BYTES   (SMEM_FLOATS * 4)      // 163840 B

// ---------------- device scratch (static: no allocations allowed) ----------------
__device__ __align__(16) float g_inp[T_STEPS * B_SZ * H_DIM];   // [T][B][H]
__device__ __align__(16) float g_S[2][H_DIM][R_ROWS];           // h-major state, double buffered
__device__ unsigned int g_bar_count;

// ---------------- packed fp32x2 FMA (FFMA2) ----------------
__device__ __forceinline__ float2 ffma2(float2 a, float2 b, float2 c) {
    unsigned long long au = *reinterpret_cast<unsigned long long*>(&a);
    unsigned long long bu = *reinterpret_cast<unsigned long long*>(&b);
    unsigned long long cu = *reinterpret_cast<unsigned long long*>(&c);
    asm("fma.rn.f32x2 %0, %1, %2, %0;" : "+l"(cu) : "l"(au), "l"(bu));
    return *reinterpret_cast<float2*>(&cu);
}

// =====================================================================
// Kernel A: inp[t][b][h] = sum_f u[t][b][f] * W_in[h][f]
// =====================================================================
#define APITCH 68
__global__ void __launch_bounds__(256) inp_gemm_kernel(const float* __restrict__ x,
                                                       const float* __restrict__ Win) {
    __shared__ float Asm[64][APITCH];
    __shared__ float Bsm[64][APITCH];

    const int tid = threadIdx.x;
    const int m0 = blockIdx.x * 64;
    const int n0 = blockIdx.y * 64;

    const int rl = tid >> 2;
    const int kq = tid & 3;

    const int txx = tid & 15;
    const int tyy = tid >> 4;

    float acc[4][4];
#pragma unroll
    for (int i = 0; i < 4; ++i)
#pragma unroll
        for (int p = 0; p < 4; ++p) acc[i][p] = 0.0f;

    const int m = m0 + rl;
    const int tt = m >> 4;
    const int bb = m & 15;

    for (int kc = 0; kc < 4; ++kc) {
        __syncthreads();
        const float* xrow = x + ((size_t)(bb * CH_SZ + kc) * T_STEPS + tt) * 64;
        const float* wrow = Win + (size_t)(n0 + rl) * K_IN + kc * 64;
#pragma unroll
        for (int q = 0; q < 4; ++q) {
            int kk = kq * 16 + q * 4;
            *reinterpret_cast<float4*>(&Asm[rl][kk]) =
                *reinterpret_cast<const float4*>(&xrow[kk]);
            *reinterpret_cast<float4*>(&Bsm[rl][kk]) =
                *reinterpret_cast<const float4*>(&wrow[kk]);
        }
        __syncthreads();

#pragma unroll 8
        for (int kk = 0; kk < 64; ++kk) {
            float a0 = Asm[4 * tyy + 0][kk];
            float a1 = Asm[4 * tyy + 1][kk];
            float a2 = Asm[4 * tyy + 2][kk];
            float a3 = Asm[4 * tyy + 3][kk];
            float b0 = Bsm[4 * txx + 0][kk];
            float b1 = Bsm[4 * txx + 1][kk];
            float b2 = Bsm[4 * txx + 2][kk];
            float b3 = Bsm[4 * txx + 3][kk];
            acc[0][0] = fmaf(a0, b0, acc[0][0]); acc[0][1] = fmaf(a0, b1, acc[0][1]);
            acc[0][2] = fmaf(a0, b2, acc[0][2]); acc[0][3] = fmaf(a0, b3, acc[0][3]);
            acc[1][0] = fmaf(a1, b0, acc[1][0]); acc[1][1] = fmaf(a1, b1, acc[1][1]);
            acc[1][2] = fmaf(a1, b2, acc[1][2]); acc[1][3] = fmaf(a1, b3, acc[1][3]);
            acc[2][0] = fmaf(a2, b0, acc[2][0]); acc[2][1] = fmaf(a2, b1, acc[2][1]);
            acc[2][2] = fmaf(a2, b2, acc[2][2]); acc[2][3] = fmaf(a2, b3, acc[2][3]);
            acc[3][0] = fmaf(a3, b0, acc[3][0]); acc[3][1] = fmaf(a3, b1, acc[3][1]);
            acc[3][2] = fmaf(a3, b2, acc[3][2]); acc[3][3] = fmaf(a3, b3, acc[3][3]);
        }
    }

#pragma unroll
    for (int i = 0; i < 4; ++i) {
        float4 v = make_float4(acc[i][0], acc[i][1], acc[i][2], acc[i][3]);
        *reinterpret_cast<float4*>(
            &g_inp[(size_t)(m0 + 4 * tyy + i) * H_DIM + n0 + 4 * txx]) = v;
    }
}

// =====================================================================
// Kernel B: persistent recurrence, register-tiled 4x4 per thread.
// =====================================================================
extern __shared__ float sm_b[];

__global__ void __launch_bounds__(NTHREADS, 1) esn_recur_kernel(
        const float* __restrict__ W_res, float* __restrict__ out) {
    float*  Wsm  = sm_b;                                     // [k][8] float2 duplicated
    float*  Ssm  = sm_b + W_FLOATS;                          // [2][CHUNK][64]
    float*  Part = sm_b + W_FLOATS + STAGE_FLOATS;           // [16 warps][512]

    const int tid  = threadIdx.x;
    const int lane = tid & 31;
    const int w    = tid >> 5;             // warp id = k-subrange within chunk
    const int rg   = lane & 15;            // rows 4rg..4rg+3
    const int cg   = lane >> 4;            // cols 4cg..4cg+3
    const int n0   = blockIdx.x * NC;

    // Preload W_res column slice, duplicated (w,w) per col: Wsm[k*16 + j*2 {+1}]
    for (int idx = tid; idx < H_DIM * NC; idx += NTHREADS) {
        int k = idx >> 3, jj = idx & 7;
        float wv = W_res[(size_t)k * H_DIM + n0 + jj];
        Wsm[k * 16 + jj * 2]     = wv;
        Wsm[k * 16 + jj * 2 + 1] = wv;
    }
    // Zero own slice of state buffer 0.
    for (int i = tid; i < NC * R_ROWS; i += NTHREADS) {
        g_S[0][n0 + (i >> 6)][i & 63] = 0.0f;
    }
    __syncthreads();

    unsigned int phase = 0;
    __threadfence();
    __syncthreads();
    if (tid == 0) {
        phase = 1;
        atomicAdd(&g_bar_count, 1u);
        while (*((volatile unsigned int*)&g_bar_count) < phase * NCTA) { }
    }
    __syncthreads();
    __threadfence();

    const size_t RS = (size_t)T_STEPS * H_DIM;
    const int c_ = tid >> 6;               // epilogue: owned col 0..7
    const int r_ = tid & 63;               // epilogue: owned row 0..63
    const int b_ = r_ >> 2;

    for (int t = 0; t < T_STEPS; ++t) {
        const float* Sprev = &g_S[t & 1][0][0];
        float*       Snext = &g_S[(t + 1) & 1][0][0];

        float2 accA[4], accB[4];
#pragma unroll
        for (int q = 0; q < 4; ++q) {
            accA[q] = make_float2(0.0f, 0.0f);
            accB[q] = make_float2(0.0f, 0.0f);
        }

        // stage chunk 0 into buffer 0
        {
            const float4* src = reinterpret_cast<const float4*>(Sprev);
            float4* dst = reinterpret_cast<float4*>(Ssm);
#pragma unroll
            for (int i = 0; i < 4; ++i)
                dst[tid + i * NTHREADS] = __ldcg(src + tid + i * NTHREADS);
        }
        __syncthreads();

#pragma unroll 1
        for (int c = 0; c < NCHUNKS; ++c) {
            // prefetch chunk c+1 into registers (LDG latency hidden by compute)
            float4 pf[4];
            if (c + 1 < NCHUNKS) {
                const float4* src = reinterpret_cast<const float4*>(
                    Sprev + (c + 1) * CHUNK * R_ROWS);
#pragma unroll
                for (int i = 0; i < 4; ++i)
                    pf[i] = __ldcg(src + tid + i * NTHREADS);
            }

            const float4* Sp = reinterpret_cast<const float4*>(
                                   Ssm + (c & 1) * (CHUNK * R_ROWS)) + w * KPW * 16 + rg;
            const float4* Wp = reinterpret_cast<const float4*>(Wsm)
                                   + (c * CHUNK + w * KPW) * 4 + cg * 2;
#pragma unroll
            for (int i = 0; i < KPW; ++i) {
                float4 s  = Sp[i * 16];
                float4 wa = Wp[i * 4];
                float4 wb = Wp[i * 4 + 1];
                float2 s01 = make_float2(s.x, s.y);
                float2 s23 = make_float2(s.z, s.w);
                accA[0] = ffma2(s01, make_float2(wa.x, wa.y), accA[0]);
                accB[0] = ffma2(s23, make_float2(wa.x, wa.y), accB[0]);
                accA[1] = ffma2(s01, make_float2(wa.z, wa.w), accA[1]);
                accB[1] = ffma2(s23, make_float2(wa.z, wa.w), accB[1]);
                accA[2] = ffma2(s01, make_float2(wb.x, wb.y), accA[2]);
                accB[2] = ffma2(s23, make_float2(wb.x, wb.y), accB[2]);
                accA[3] = ffma2(s01, make_float2(wb.z, wb.w), accA[3]);
                accB[3] = ffma2(s23, make_float2(wb.z, wb.w), accB[3]);
            }

            // commit prefetched chunk to the other buffer
            if (c + 1 < NCHUNKS) {
                float4* dst = reinterpret_cast<float4*>(
                    Ssm + ((c + 1) & 1) * (CHUNK * R_ROWS));
#pragma unroll
                for (int i = 0; i < 4; ++i)
                    dst[tid + i * NTHREADS] = pf[i];
            }
            __syncthreads();
        }

        // ---- write k-split partials: layout Part[w][c*64 + r] (float4 over rows) ----
        {
            float4* P4 = reinterpret_cast<float4*>(Part) + w * 128;
#pragma unroll
            for (int q = 0; q < 4; ++q) {
                P4[(4 * cg + q) * 16 + rg] =
                    make_float4(accA[q].x, accA[q].y, accB[q].x, accB[q].y);
            }
        }
        __syncthreads();

        // ---- reduce 16 partials, one output per thread ----
        float sum = 0.0f;
#pragma unroll
        for (int ww = 0; ww < NW; ++ww)
            sum += Part[ww * (R_ROWS * NC) + tid];

        float inp_v = g_inp[(size_t)(t * B_SZ + b_) * H_DIM + n0 + c_];
        float sp = __ldcg(Sprev + (size_t)(n0 + c_) * R_ROWS + r_);
        float val = 0.9f * tanhf(inp_v + sum) + 0.1f * sp;

        Snext[(size_t)(n0 + c_) * R_ROWS + r_] = val;

        // ---- barrier arrive (state visible); overlap out store with wait ----
        __threadfence();
        __syncthreads();
        if (tid == 0) {
            phase += 1;
            atomicAdd(&g_bar_count, 1u);
        }

        out[(size_t)r_ * RS + (size_t)t * H_DIM + n0 + c_] = val;

        if (tid == 0) {
            unsigned int target = phase * NCTA;
            while (*((volatile unsigned int*)&g_bar_count) < target) { }
        }
        __syncthreads();
        __threadfence();
    }
}

// =====================================================================
// launch
// =====================================================================
extern "C" void kernel_launch(void* const* d_in, const int* in_sizes, int n_in,
                              void* d_out, int out_size) {
    const float* x    = (const float*)d_in[0];   // [16,4,1024,64]
    const float* Win  = (const float*)d_in[1];   // [1024,256]
    const float* Wres = (const float*)d_in[2];   // [1024,1024]
    float* out = (float*)d_out;                  // [16,4,1024,1024]

    cudaFuncSetAttribute(esn_recur_kernel,
                         cudaFuncAttributeMaxDynamicSharedMemorySize, SMEM_BYTES);

    // input projection (off critical path)
    inp_gemm_kernel<<<dim3(256, 16), 256>>>(x, Win);

    // reset grid barrier counter (captured as a memset node)
    void* bp = nullptr;
    cudaGetSymbolAddress(&bp, g_bar_count);
    cudaMemsetAsync(bp, 0, sizeof(unsigned int));

    // persistent recurrence
    esn_recur_kernel<<<NCTA, NTHREADS, SMEM_BYTES>>>(Wres, out);
}

// round 11
// speedup vs baseline: 2.3749x; 1.3726x over previous
#include <cuda_runtime.h>

// ---------------- problem constants ----------------
#define T_STEPS   1024
#define H_DIM     1024
#define B_SZ      16
#define CH_SZ     4
#define R_ROWS    64            // B*CH rows of the state matrix
#define K_IN      256           // CH * D

// ---------------- recurrence kernel config ----------------
#define NCTA      128
#define NC        8             // H_DIM / NCTA columns owned per CTA
#define NTHREADS  512           // 16 warps
#define NW        16
#define KW        (H_DIM / NW)  // 64 contiguous k per warp

// SMEM floats: duplicated weights [1024][16] = 16384, partials 16*512 = 8192
#define W_FLOATS     (H_DIM * NC * 2)
#define PART_FLOATS  (NW * R_ROWS * NC)
#define SMEM_FLOATS  (W_FLOATS + PART_FLOATS)
#define SMEM_BYTES   (SMEM_FLOATS * 4)      // 98304 B

// ---------------- device scratch (static: no allocations allowed) ----------------
__device__ __align__(16) float g_inp[T_STEPS * B_SZ * H_DIM];   // [T][B][H]
__device__ __align__(16) float g_S[2][H_DIM][R_ROWS];           // h-major state, double buffered
__device__ unsigned int g_bar_count;

// ---------------- packed fp32x2 FMA (FFMA2) ----------------
__device__ __forceinline__ float2 ffma2(float2 a, float2 b, float2 c) {
    unsigned long long au = *reinterpret_cast<unsigned long long*>(&a);
    unsigned long long bu = *reinterpret_cast<unsigned long long*>(&b);
    unsigned long long cu = *reinterpret_cast<unsigned long long*>(&c);
    asm("fma.rn.f32x2 %0, %1, %2, %0;" : "+l"(cu) : "l"(au), "l"(bu));
    return *reinterpret_cast<float2*>(&cu);
}

// =====================================================================
// Kernel A: inp[t][b][h] = sum_f u[t][b][f] * W_in[h][f]
// =====================================================================
#define APITCH 68
__global__ void __launch_bounds__(256) inp_gemm_kernel(const float* __restrict__ x,
                                                       const float* __restrict__ Win) {
    __shared__ float Asm[64][APITCH];
    __shared__ float Bsm[64][APITCH];

    const int tid = threadIdx.x;
    const int m0 = blockIdx.x * 64;
    const int n0 = blockIdx.y * 64;

    const int rl = tid >> 2;
    const int kq = tid & 3;

    const int txx = tid & 15;
    const int tyy = tid >> 4;

    float acc[4][4];
#pragma unroll
    for (int i = 0; i < 4; ++i)
#pragma unroll
        for (int p = 0; p < 4; ++p) acc[i][p] = 0.0f;

    const int m = m0 + rl;
    const int tt = m >> 4;
    const int bb = m & 15;

    for (int kc = 0; kc < 4; ++kc) {
        __syncthreads();
        const float* xrow = x + ((size_t)(bb * CH_SZ + kc) * T_STEPS + tt) * 64;
        const float* wrow = Win + (size_t)(n0 + rl) * K_IN + kc * 64;
#pragma unroll
        for (int q = 0; q < 4; ++q) {
            int kk = kq * 16 + q * 4;
            *reinterpret_cast<float4*>(&Asm[rl][kk]) =
                *reinterpret_cast<const float4*>(&xrow[kk]);
            *reinterpret_cast<float4*>(&Bsm[rl][kk]) =
                *reinterpret_cast<const float4*>(&wrow[kk]);
        }
        __syncthreads();

#pragma unroll 8
        for (int kk = 0; kk < 64; ++kk) {
            float a0 = Asm[4 * tyy + 0][kk];
            float a1 = Asm[4 * tyy + 1][kk];
            float a2 = Asm[4 * tyy + 2][kk];
            float a3 = Asm[4 * tyy + 3][kk];
            float b0 = Bsm[4 * txx + 0][kk];
            float b1 = Bsm[4 * txx + 1][kk];
            float b2 = Bsm[4 * txx + 2][kk];
            float b3 = Bsm[4 * txx + 3][kk];
            acc[0][0] = fmaf(a0, b0, acc[0][0]); acc[0][1] = fmaf(a0, b1, acc[0][1]);
            acc[0][2] = fmaf(a0, b2, acc[0][2]); acc[0][3] = fmaf(a0, b3, acc[0][3]);
            acc[1][0] = fmaf(a1, b0, acc[1][0]); acc[1][1] = fmaf(a1, b1, acc[1][1]);
            acc[1][2] = fmaf(a1, b2, acc[1][2]); acc[1][3] = fmaf(a1, b3, acc[1][3]);
            acc[2][0] = fmaf(a2, b0, acc[2][0]); acc[2][1] = fmaf(a2, b1, acc[2][1]);
            acc[2][2] = fmaf(a2, b2, acc[2][2]); acc[2][3] = fmaf(a2, b3, acc[2][3]);
            acc[3][0] = fmaf(a3, b0, acc[3][0]); acc[3][1] = fmaf(a3, b1, acc[3][1]);
            acc[3][2] = fmaf(a3, b2, acc[3][2]); acc[3][3] = fmaf(a3, b3, acc[3][3]);
        }
    }

#pragma unroll
    for (int i = 0; i < 4; ++i) {
        float4 v = make_float4(acc[i][0], acc[i][1], acc[i][2], acc[i][3]);
        *reinterpret_cast<float4*>(
            &g_inp[(size_t)(m0 + 4 * tyy + i) * H_DIM + n0 + 4 * txx]) = v;
    }
}

// =====================================================================
// Kernel B: persistent recurrence; direct-LDG state reads, no staging.
// =====================================================================
extern __shared__ float sm_b[];

__device__ __forceinline__ void mac_block(const float4 s, const float4* __restrict__ Wp,
                                          float2* accA, float2* accB) {
    float4 wa = Wp[0];
    float4 wb = Wp[1];
    float2 s01 = make_float2(s.x, s.y);
    float2 s23 = make_float2(s.z, s.w);
    accA[0] = ffma2(s01, make_float2(wa.x, wa.y), accA[0]);
    accB[0] = ffma2(s23, make_float2(wa.x, wa.y), accB[0]);
    accA[1] = ffma2(s01, make_float2(wa.z, wa.w), accA[1]);
    accB[1] = ffma2(s23, make_float2(wa.z, wa.w), accB[1]);
    accA[2] = ffma2(s01, make_float2(wb.x, wb.y), accA[2]);
    accB[2] = ffma2(s23, make_float2(wb.x, wb.y), accB[2]);
    accA[3] = ffma2(s01, make_float2(wb.z, wb.w), accA[3]);
    accB[3] = ffma2(s23, make_float2(wb.z, wb.w), accB[3]);
}

__global__ void __launch_bounds__(NTHREADS, 1) esn_recur_kernel(
        const float* __restrict__ W_res, float* __restrict__ out) {
    float* Wsm  = sm_b;                 // duplicated weights: [k][16] (8 cols x2)
    float* Part = sm_b + W_FLOATS;      // [16 warps][512]

    const int tid  = threadIdx.x;
    const int lane = tid & 31;
    const int w    = tid >> 5;             // warp id -> k range [w*64, w*64+64)
    const int rg   = lane & 15;            // rows 4rg..4rg+3
    const int cg   = lane >> 4;            // cols 4cg..4cg+3
    const int n0   = blockIdx.x * NC;

    // Preload W_res column slice, duplicated (w,w) per col.
    for (int idx = tid; idx < H_DIM * NC; idx += NTHREADS) {
        int k = idx >> 3, jj = idx & 7;
        float wv = W_res[(size_t)k * H_DIM + n0 + jj];
        Wsm[k * 16 + jj * 2]     = wv;
        Wsm[k * 16 + jj * 2 + 1] = wv;
    }
    // Zero own slice of state buffer 0.
    for (int i = tid; i < NC * R_ROWS; i += NTHREADS) {
        g_S[0][n0 + (i >> 6)][i & 63] = 0.0f;
    }
    __syncthreads();

    unsigned int phase = 0;
    __threadfence();
    __syncthreads();
    if (tid == 0) {
        phase = 1;
        atomicAdd(&g_bar_count, 1u);
        while (*((volatile unsigned int*)&g_bar_count) < phase * NCTA) { }
    }
    __syncthreads();
    __threadfence();

    const size_t RS = (size_t)T_STEPS * H_DIM;
    const int c_ = tid >> 6;               // epilogue: owned col 0..7
    const int r_ = tid & 63;               // epilogue: owned row 0..63
    const int b_ = r_ >> 2;

    float my_state = 0.0f;                 // this thread's state element (prev step)

    const float4* Wp4 = reinterpret_cast<const float4*>(Wsm) + (w * KW) * 4 + cg * 2;

    for (int t = 0; t < T_STEPS; ++t) {
        const float* Sprev = &g_S[t & 1][0][0];
        float*       Snext = &g_S[(t + 1) & 1][0][0];

        float2 accA[4], accB[4];
#pragma unroll
        for (int q = 0; q < 4; ++q) {
            accA[q] = make_float2(0.0f, 0.0f);
            accB[q] = make_float2(0.0f, 0.0f);
        }

        // warp's state rows: Sprev row k = 16 float4; lane reads float4 #rg
        const float4* Sg = reinterpret_cast<const float4*>(Sprev) + (w * KW) * 16 + rg;

        float4 cur[4], nxt[4];
#pragma unroll
        for (int i = 0; i < 4; ++i) cur[i] = __ldcg(Sg + i * 16);

#pragma unroll
        for (int kb = 0; kb < KW; kb += 8) {
            // prefetch k = kb+4 .. kb+7
#pragma unroll
            for (int i = 0; i < 4; ++i) nxt[i] = __ldcg(Sg + (kb + 4 + i) * 16);
            // compute k = kb .. kb+3
#pragma unroll
            for (int i = 0; i < 4; ++i)
                mac_block(cur[i], Wp4 + (kb + i) * 4, accA, accB);
            // prefetch k = kb+8 .. kb+11
            if (kb + 8 < KW) {
#pragma unroll
                for (int i = 0; i < 4; ++i) cur[i] = __ldcg(Sg + (kb + 8 + i) * 16);
            }
            // compute k = kb+4 .. kb+7
#pragma unroll
            for (int i = 0; i < 4; ++i)
                mac_block(nxt[i], Wp4 + (kb + 4 + i) * 4, accA, accB);
        }

        // ---- write k-split partials: Part[w][col*64 + row], float4 over rows ----
        {
            float4* P4 = reinterpret_cast<float4*>(Part) + w * 128;
#pragma unroll
            for (int q = 0; q < 4; ++q) {
                P4[(4 * cg + q) * 16 + rg] =
                    make_float4(accA[q].x, accA[q].y, accB[q].x, accB[q].y);
            }
        }
        __syncthreads();

        // ---- reduce 16 partials, one output per thread ----
        float sum = 0.0f;
#pragma unroll
        for (int ww = 0; ww < NW; ++ww)
            sum += Part[ww * (R_ROWS * NC) + tid];

        float inp_v = __ldg(&g_inp[(size_t)(t * B_SZ + b_) * H_DIM + n0 + c_]);
        float val = 0.9f * tanhf(inp_v + sum) + 0.1f * my_state;
        my_state = val;

        __stcg(&Snext[(size_t)(n0 + c_) * R_ROWS + r_], val);

        // ---- barrier arrive (state visible); overlap out store with wait ----
        __threadfence();
        __syncthreads();
        if (tid == 0) {
            phase += 1;
            atomicAdd(&g_bar_count, 1u);
        }

        out[(size_t)r_ * RS + (size_t)t * H_DIM + n0 + c_] = val;

        if (tid == 0) {
            unsigned int target = phase * NCTA;
            while (*((volatile unsigned int*)&g_bar_count) < target) { }
        }
        __syncthreads();
        __threadfence();
    }
}

// =====================================================================
// launch
// =====================================================================
extern "C" void kernel_launch(void* const* d_in, const int* in_sizes, int n_in,
                              void* d_out, int out_size) {
    const float* x    = (const float*)d_in[0];   // [16,4,1024,64]
    const float* Win  = (const float*)d_in[1];   // [1024,256]
    const float* Wres = (const float*)d_in[2];   // [1024,1024]
    float* out = (float*)d_out;                  // [16,4,1024,1024]

    cudaFuncSetAttribute(esn_recur_kernel,
                         cudaFuncAttributeMaxDynamicSharedMemorySize, SMEM_BYTES);

    // input projection (off critical path)
    inp_gemm_kernel<<<dim3(256, 16), 256>>>(x, Win);

    // reset grid barrier counter (captured as a memset node)
    void* bp = nullptr;
    cudaGetSymbolAddress(&bp, g_bar_count);
    cudaMemsetAsync(bp, 0, sizeof(unsigned int));

    // persistent recurrence
    esn_recur_kernel<<<NCTA, NTHREADS, SMEM_BYTES>>>(Wres, out);
}